// round 5
// baseline (speedup 1.0000x reference)
#include <cuda_runtime.h>
#include <math.h>

#define NN 6144
#define NFEAT 512
#define NHID 256
#define NCLASS 8
#define ADIM 128

// ---------------- scratch (device globals; no allocation allowed) ----------
__device__ float g_adj[(size_t)NN * NN];   // combined adjacency          151 MB
__device__ float g_S[(size_t)NN * NN];     // scores -> attention         151 MB
__device__ float g_Z[NN * 3 * ADIM];       // [z1|z2|z3]                  9.4 MB
__device__ float g_nz[NN * 3];
__device__ float g_XW1[NN * NHID];
__device__ float g_x[NN * NHID];
__device__ float g_Q[NN * NHID];
__device__ float g_Kh[NN * NHID];
__device__ float g_V[NN * NHID];
__device__ float g_Xt[NN * NHID];
__device__ float g_XW2[NN * NCLASS];

// ---------------- tiled fp32 GEMM core -------------------------------------
// C[bm:bm+BM, bn:bn+BN] = A[M,K] @ B  (+bias)(+relu)
// trB==0: B is [K, ldb] row-major, use columns bn..  ; trB==1: B is [Nb, K], C = A @ B^T
// epi bit0 = add bias[col], bit1 = relu
template<int BM, int BN, int BK, int TM, int TN>
__device__ __forceinline__ void gemm_core(
    const float* __restrict__ A, int lda,
    const float* __restrict__ B, int ldb,
    const float* __restrict__ bias,
    float* __restrict__ C, int ldc,
    int K, int bm, int bn, int epi, int trB)
{
    __shared__ float As[BK][BM + 4];
    __shared__ float Bs[BK][BN + 4];
    const int tid = threadIdx.x;
    const int tx = tid % (BN / TN);
    const int ty = tid / (BN / TN);

    float acc[TM][TN];
#pragma unroll
    for (int i = 0; i < TM; i++)
#pragma unroll
        for (int j = 0; j < TN; j++) acc[i][j] = 0.0f;

    for (int k0 = 0; k0 < K; k0 += BK) {
        {   // A tile: BM x BK, stored transposed As[k][m]
            constexpr int PER = (BM * BK / 4) / 256;
#pragma unroll
            for (int i = 0; i < PER; i++) {
                int idx = tid + i * 256;
                int row = idx / (BK / 4);
                int c4  = idx % (BK / 4);
                float4 v = *reinterpret_cast<const float4*>(
                    A + (size_t)(bm + row) * lda + k0 + c4 * 4);
                As[c4 * 4 + 0][row] = v.x; As[c4 * 4 + 1][row] = v.y;
                As[c4 * 4 + 2][row] = v.z; As[c4 * 4 + 3][row] = v.w;
            }
        }
        if (!trB) {  // B tile: BK x BN direct
            constexpr int PER = (BK * BN / 4) / 256;
#pragma unroll
            for (int i = 0; i < PER; i++) {
                int idx = tid + i * 256;
                int row = idx / (BN / 4);
                int c4  = idx % (BN / 4);
                float4 v = *reinterpret_cast<const float4*>(
                    B + (size_t)(k0 + row) * ldb + bn + c4 * 4);
                *reinterpret_cast<float4*>(&Bs[row][c4 * 4]) = v;
            }
        } else {     // B tile from B[N,K]: Bs[k][n] = B[bn+n][k0+k]
            constexpr int PER = (BK * BN / 4) / 256;
#pragma unroll
            for (int i = 0; i < PER; i++) {
                int idx = tid + i * 256;
                int n   = idx / (BK / 4);
                int c4  = idx % (BK / 4);
                float4 v = *reinterpret_cast<const float4*>(
                    B + (size_t)(bn + n) * ldb + k0 + c4 * 4);
                Bs[c4 * 4 + 0][n] = v.x; Bs[c4 * 4 + 1][n] = v.y;
                Bs[c4 * 4 + 2][n] = v.z; Bs[c4 * 4 + 3][n] = v.w;
            }
        }
        __syncthreads();
#pragma unroll
        for (int kk = 0; kk < BK; kk++) {
            float af[TM], bf[TN];
#pragma unroll
            for (int i = 0; i < TM; i += 4) {
                float4 v = *reinterpret_cast<const float4*>(&As[kk][ty * TM + i]);
                af[i] = v.x; af[i + 1] = v.y; af[i + 2] = v.z; af[i + 3] = v.w;
            }
#pragma unroll
            for (int j = 0; j < TN; j += 4) {
                float4 v = *reinterpret_cast<const float4*>(&Bs[kk][tx * TN + j]);
                bf[j] = v.x; bf[j + 1] = v.y; bf[j + 2] = v.z; bf[j + 3] = v.w;
            }
#pragma unroll
            for (int i = 0; i < TM; i++)
#pragma unroll
                for (int j = 0; j < TN; j++)
                    acc[i][j] = fmaf(af[i], bf[j], acc[i][j]);
        }
        __syncthreads();
    }

#pragma unroll
    for (int i = 0; i < TM; i++) {
        int row = bm + ty * TM + i;
#pragma unroll
        for (int j = 0; j < TN; j += 4) {
            int col = bn + tx * TN + j;
            float4 v;
            v.x = acc[i][j]; v.y = acc[i][j + 1]; v.z = acc[i][j + 2]; v.w = acc[i][j + 3];
            if (epi & 1) {
                v.x += bias[col]; v.y += bias[col + 1];
                v.z += bias[col + 2]; v.w += bias[col + 3];
            }
            if (epi & 2) {
                v.x = fmaxf(v.x, 0.f); v.y = fmaxf(v.y, 0.f);
                v.z = fmaxf(v.z, 0.f); v.w = fmaxf(v.w, 0.f);
            }
            *reinterpret_cast<float4*>(C + (size_t)row * ldc + col) = v;
        }
    }
}

template<int BM, int BN, int BK, int TM, int TN>
__global__ __launch_bounds__(256)
void gemm_kernel(const float* __restrict__ A, int lda,
                 const float* __restrict__ B, int ldb,
                 const float* __restrict__ bias,
                 float* __restrict__ C, int ldc,
                 int K, int epi, int trB)
{
    gemm_core<BM, BN, BK, TM, TN>(A, lda, B, ldb, bias, C, ldc, K,
                                  blockIdx.x * BM, blockIdx.y * BN, epi, trB);
}

// z1|z2|z3 fused into one launch (blockIdx.z selects adjacency/weights)
__global__ __launch_bounds__(256)
void gemm_z3_kernel(const float* a0, const float* a1, const float* a2,
                    const float* w0, const float* w1, const float* w2,
                    const float* bb0, const float* bb1, const float* bb2)
{
    int z = blockIdx.z;
    const float* A  = (z == 0) ? a0  : ((z == 1) ? a1  : a2);
    const float* B  = (z == 0) ? w0  : ((z == 1) ? w1  : w2);
    const float* bi = (z == 0) ? bb0 : ((z == 1) ? bb1 : bb2);
    gemm_core<128, 128, 16, 8, 8>(A, NN, B, ADIM, bi, g_Z + z * ADIM, 3 * ADIM,
                                  NN, blockIdx.x * 128, 0, /*epi=*/1, /*trB=*/0);
}

// ---------------- agg Linear(384->3) + softmax -> nz ------------------------
__global__ __launch_bounds__(256)
void agg_softmax_kernel(const float* __restrict__ Wagg,
                        const float* __restrict__ bagg,
                        float* __restrict__ out_nz)
{
    __shared__ float sW[3 * ADIM * 3];
    int tid = threadIdx.x;
    for (int i = tid; i < 3 * ADIM * 3; i += 256) sW[i] = Wagg[i];
    __syncthreads();
    int warp = tid >> 5, lane = tid & 31;
    int row = blockIdx.x * 8 + warp;
    const float* zr = g_Z + (size_t)row * (3 * ADIM);
    float p0 = 0.f, p1 = 0.f, p2 = 0.f;
#pragma unroll
    for (int it = 0; it < (3 * ADIM) / 32; it++) {
        int k = it * 32 + lane;
        float zv = zr[k];
        p0 = fmaf(zv, sW[k * 3 + 0], p0);
        p1 = fmaf(zv, sW[k * 3 + 1], p1);
        p2 = fmaf(zv, sW[k * 3 + 2], p2);
    }
#pragma unroll
    for (int off = 16; off; off >>= 1) {
        p0 += __shfl_xor_sync(0xffffffffu, p0, off);
        p1 += __shfl_xor_sync(0xffffffffu, p1, off);
        p2 += __shfl_xor_sync(0xffffffffu, p2, off);
    }
    if (lane == 0) {
        p0 += bagg[0]; p1 += bagg[1]; p2 += bagg[2];
        float m = fmaxf(p0, fmaxf(p1, p2));
        float e0 = __expf(p0 - m), e1 = __expf(p1 - m), e2 = __expf(p2 - m);
        float inv = 1.f / (e0 + e1 + e2);
        float n0 = e0 * inv, n1 = e1 * inv, n2 = e2 * inv;
        g_nz[row * 3 + 0] = n0; g_nz[row * 3 + 1] = n1; g_nz[row * 3 + 2] = n2;
        if (out_nz) {
            out_nz[row * 3 + 0] = n0; out_nz[row * 3 + 1] = n1; out_nz[row * 3 + 2] = n2;
        }
    }
}

// ---------------- adj[r,c] = sum_i nz[c,i] * adj_i[r,c] (columns scaled) ----
__global__ __launch_bounds__(256)
void combine_adj_kernel(const float* __restrict__ a0,
                        const float* __restrict__ a1,
                        const float* __restrict__ a2)
{
    size_t idx = (size_t)blockIdx.x * 256 + threadIdx.x;   // float4 index
    int c = (int)(idx % (NN / 4)) * 4;
    float4 v0 = ((const float4*)a0)[idx];
    float4 v1 = ((const float4*)a1)[idx];
    float4 v2 = ((const float4*)a2)[idx];
    float4 r;
    r.x = g_nz[(c + 0) * 3] * v0.x + g_nz[(c + 0) * 3 + 1] * v1.x + g_nz[(c + 0) * 3 + 2] * v2.x;
    r.y = g_nz[(c + 1) * 3] * v0.y + g_nz[(c + 1) * 3 + 1] * v1.y + g_nz[(c + 1) * 3 + 2] * v2.y;
    r.z = g_nz[(c + 2) * 3] * v0.z + g_nz[(c + 2) * 3 + 1] * v1.z + g_nz[(c + 2) * 3 + 2] * v2.z;
    r.w = g_nz[(c + 3) * 3] * v0.w + g_nz[(c + 3) * 3 + 1] * v1.w + g_nz[(c + 3) * 3 + 2] * v2.w;
    ((float4*)g_adj)[idx] = r;
}

// ---------------- masked row-softmax: g_S <- softmax_row(g_adj * g_S) -------
// (_gcn_norm of a row-softmax is identity to ~1e-9; skipped.)
__global__ __launch_bounds__(256)
void att_softmax_kernel()
{
    __shared__ float sv[NN];
    __shared__ float red[8];
    int row = blockIdx.x, tid = threadIdx.x;
    const float* ar = g_adj + (size_t)row * NN;
    float* sr = g_S + (size_t)row * NN;

    float m = -3.4e38f;
    for (int j = tid; j < NN; j += 256) {
        float v = ar[j] * sr[j];
        sv[j] = v;
        m = fmaxf(m, v);
    }
#pragma unroll
    for (int off = 16; off; off >>= 1) m = fmaxf(m, __shfl_xor_sync(0xffffffffu, m, off));
    if ((tid & 31) == 0) red[tid >> 5] = m;
    __syncthreads();
    float M = -3.4e38f;
#pragma unroll
    for (int i = 0; i < 8; i++) M = fmaxf(M, red[i]);
    __syncthreads();

    float s = 0.f;
    for (int j = tid; j < NN; j += 256) {
        float e = __expf(sv[j] - M);
        sv[j] = e;
        s += e;
    }
#pragma unroll
    for (int off = 16; off; off >>= 1) s += __shfl_xor_sync(0xffffffffu, s, off);
    if ((tid & 31) == 0) red[tid >> 5] = s;
    __syncthreads();
    float S = 0.f;
#pragma unroll
    for (int i = 0; i < 8; i++) S += red[i];
    float inv = 1.f / S;

    for (int j = tid; j < NN; j += 256) sr[j] = sv[j] * inv;
}

// ---------------- XW2 = X_tilde @ W2  (N=8) ---------------------------------
__global__ __launch_bounds__(256)
void xw2_kernel(const float* __restrict__ W2)
{
    __shared__ float sW[NHID][9];  // pitch 9 -> conflict-free strided reads
    int tid = threadIdx.x;
    for (int i = tid; i < NHID * NCLASS; i += 256) sW[i / 8][i % 8] = W2[i];
    __syncthreads();
    int warp = tid >> 5, lane = tid & 31;
    int row = blockIdx.x * 8 + warp;
    const float* xr = g_Xt + (size_t)row * NHID;
    float acc[8] = {0, 0, 0, 0, 0, 0, 0, 0};
#pragma unroll
    for (int it = 0; it < NHID / 32; it++) {
        int k = it * 32 + lane;
        float xv = xr[k];
#pragma unroll
        for (int j = 0; j < 8; j++) acc[j] = fmaf(xv, sW[k][j], acc[j]);
    }
#pragma unroll
    for (int j = 0; j < 8; j++)
#pragma unroll
        for (int off = 16; off; off >>= 1)
            acc[j] += __shfl_xor_sync(0xffffffffu, acc[j], off);
    if (lane == 0) {
#pragma unroll
        for (int j = 0; j < 8; j++) g_XW2[(size_t)row * 8 + j] = acc[j];
    }
}

// ---------------- z = adj @ XW2 + b2 ; softmax rows -> out ------------------
__global__ __launch_bounds__(256)
void z_out_kernel(const float* __restrict__ b2, float* __restrict__ out)
{
    __shared__ float sW[512][9];
    int tid = threadIdx.x, warp = tid >> 5, lane = tid & 31;
    int row = blockIdx.x * 8 + warp;
    const float* ar = g_adj + (size_t)row * NN;
    float acc[8] = {0, 0, 0, 0, 0, 0, 0, 0};
    for (int c0 = 0; c0 < NN; c0 += 512) {
        __syncthreads();
        for (int i = tid; i < 512 * 8; i += 256) sW[i / 8][i % 8] = g_XW2[(size_t)(c0) * 8 + i];
        __syncthreads();
#pragma unroll
        for (int it = 0; it < 16; it++) {
            int k = it * 32 + lane;
            float a = ar[c0 + k];
#pragma unroll
            for (int j = 0; j < 8; j++) acc[j] = fmaf(a, sW[k][j], acc[j]);
        }
    }
#pragma unroll
    for (int j = 0; j < 8; j++)
#pragma unroll
        for (int off = 16; off; off >>= 1)
            acc[j] += __shfl_xor_sync(0xffffffffu, acc[j], off);
    if (lane == 0) {
        float z[8]; float m = -3.4e38f;
#pragma unroll
        for (int j = 0; j < 8; j++) { z[j] = acc[j] + b2[j]; m = fmaxf(m, z[j]); }
        float s = 0.f;
#pragma unroll
        for (int j = 0; j < 8; j++) { z[j] = __expf(z[j] - m); s += z[j]; }
        float inv = 1.f / s;
#pragma unroll
        for (int j = 0; j < 8; j++) out[(size_t)row * 8 + j] = z[j] * inv;
    }
}

// ---------------- launch ----------------------------------------------------
extern "C" void kernel_launch(void* const* d_in, const int* in_sizes, int n_in,
                              void* d_out, int out_size)
{
    const float* adj0 = (const float*)d_in[0];
    const float* adj1 = (const float*)d_in[1];
    const float* adj2 = (const float*)d_in[2];
    const float* feat = (const float*)d_in[3];
    const float* Wa1  = (const float*)d_in[4];
    const float* ba1  = (const float*)d_in[5];
    const float* Wa2  = (const float*)d_in[6];
    const float* ba2  = (const float*)d_in[7];
    const float* Wa3  = (const float*)d_in[8];
    const float* ba3  = (const float*)d_in[9];
    const float* Wagg = (const float*)d_in[10];
    const float* bagg = (const float*)d_in[11];
    const float* W1   = (const float*)d_in[12];
    const float* b1   = (const float*)d_in[13];
    const float* Wq   = (const float*)d_in[14];
    const float* bq   = (const float*)d_in[15];
    const float* Wk   = (const float*)d_in[16];
    const float* bk   = (const float*)d_in[17];
    const float* Wv   = (const float*)d_in[18];
    const float* bv   = (const float*)d_in[19];
    const float* W2   = (const float*)d_in[20];
    const float* b2   = (const float*)d_in[21];
    float* out = (float*)d_out;

    float *adjC, *S, *XW1, *x, *Q, *Kh, *V, *Xt;
    cudaGetSymbolAddress((void**)&adjC, g_adj);
    cudaGetSymbolAddress((void**)&S,    g_S);
    cudaGetSymbolAddress((void**)&XW1,  g_XW1);
    cudaGetSymbolAddress((void**)&x,    g_x);
    cudaGetSymbolAddress((void**)&Q,    g_Q);
    cudaGetSymbolAddress((void**)&Kh,   g_Kh);
    cudaGetSymbolAddress((void**)&V,    g_V);
    cudaGetSymbolAddress((void**)&Xt,   g_Xt);

    // 1) z1|z2|z3 : three [N,N]@[N,128] GEMMs in one launch (144 blocks)
    gemm_z3_kernel<<<dim3(48, 1, 3), 256>>>(adj0, adj1, adj2, Wa1, Wa2, Wa3, ba1, ba2, ba3);

    // 2) nz = softmax(concat(z)@Wagg + bagg); also second output
    float* out_nz = (out_size >= NN * (NCLASS + 3)) ? out + (size_t)NN * NCLASS : nullptr;
    agg_softmax_kernel<<<NN / 8, 256>>>(Wagg, bagg, out_nz);

    // 3) adj = column-weighted combination
    combine_adj_kernel<<<(NN / 4) * (NN / 256), 256>>>(adj0, adj1, adj2);

    // 4) XW1 = features @ W1
    gemm_kernel<64, 128, 16, 4, 8><<<dim3(NN / 64, NHID / 128), 256>>>(
        feat, NFEAT, W1, NHID, nullptr, XW1, NHID, NFEAT, 0, 0);

    // 5) x = relu(adj @ XW1 + b1)
    gemm_kernel<64, 128, 16, 4, 8><<<dim3(NN / 64, NHID / 128), 256>>>(
        adjC, NN, XW1, NHID, b1, x, NHID, NN, 3, 0);

    // 6) Q, K, V
    gemm_kernel<64, 128, 16, 4, 8><<<dim3(NN / 64, NHID / 128), 256>>>(
        x, NHID, Wq, NHID, bq, Q, NHID, NHID, 1, 0);
    gemm_kernel<64, 128, 16, 4, 8><<<dim3(NN / 64, NHID / 128), 256>>>(
        x, NHID, Wk, NHID, bk, Kh, NHID, NHID, 1, 0);
    gemm_kernel<64, 128, 16, 4, 8><<<dim3(NN / 64, NHID / 128), 256>>>(
        x, NHID, Wv, NHID, bv, V, NHID, NHID, 1, 0);

    // 7) S = Q @ K^T  (must stay fp32: scores ~1e4, softmax is near-one-hot)
    gemm_kernel<128, 128, 16, 8, 8><<<dim3(NN / 128, NN / 128), 256>>>(
        Q, NHID, Kh, NHID, nullptr, S, NN, NHID, 0, 1);

    // 8) attention = row-softmax(adj * S)   (gcn_norm == identity, skipped)
    att_softmax_kernel<<<NN, 256>>>();

    // 9) X_tilde = relu(attention @ V)
    gemm_kernel<64, 128, 16, 4, 8><<<dim3(NN / 64, NHID / 128), 256>>>(
        S, NN, V, NHID, nullptr, Xt, NHID, NN, 2, 0);

    // 10) XW2 = X_tilde @ W2
    xw2_kernel<<<NN / 8, 256>>>(W2);

    // 11) z = adj @ XW2 + b2 ; row softmax -> out[0 : N*8)
    z_out_kernel<<<NN / 8, 256>>>(b2, out);
}

// round 7
// speedup vs baseline: 3.2299x; 3.2299x over previous
#include <cuda_runtime.h>
#include <cuda_bf16.h>
#include <cstdint>
#include <math.h>

#define NN 6144
#define NFEAT 512
#define NHID 256
#define NCLASS 8
#define ADIM 128

// ---------------- scratch (device globals; no allocation allowed) ----------
__device__ float g_adj[(size_t)NN * NN];   // combined adjacency
__device__ float g_S[(size_t)NN * NN];     // scores -> attention (in-place)
__device__ float g_Z[NN * 3 * ADIM];
__device__ float g_nz[NN * 3];
__device__ float g_XW1[NN * NHID];
__device__ float g_XW1T[NHID * NN];
__device__ float g_x[NN * NHID];
__device__ float g_Q[NN * NHID];
__device__ float g_Kh[NN * NHID];
__device__ float g_V[NN * NHID];
__device__ float g_VT[NHID * NN];
__device__ float g_Xt[NN * NHID];
__device__ float g_XW2[NN * NCLASS];
__device__ float g_WaT[3][ADIM * NN];
__device__ float g_W1T[NHID * NFEAT];
__device__ float g_WqT[NHID * NHID];
__device__ float g_WkT[NHID * NHID];
__device__ float g_WvT[NHID * NHID];

// ================= helpers ==================================================
__device__ __forceinline__ uint32_t smem_to_u32(const void* p) {
    uint32_t a;
    asm("{ .reg .u64 t; cvta.to.shared.u64 t, %1; cvt.u32.u64 %0, t; }" : "=r"(a) : "l"(p));
    return a;
}

// split fp32 x4 -> bf16 hi pair + lo pair (lo = exact residual, re-rounded)
__device__ __forceinline__ void split4(float4 v, uint2& hi, uint2& lo) {
    uint32_t h0, h1, l0, l1;
    asm("cvt.rn.bf16x2.f32 %0, %1, %2;" : "=r"(h0) : "f"(v.y), "f"(v.x));
    asm("cvt.rn.bf16x2.f32 %0, %1, %2;" : "=r"(h1) : "f"(v.w), "f"(v.z));
    float r0 = v.x - __uint_as_float(h0 << 16);
    float r1 = v.y - __uint_as_float(h0 & 0xffff0000u);
    float r2 = v.z - __uint_as_float(h1 << 16);
    float r3 = v.w - __uint_as_float(h1 & 0xffff0000u);
    asm("cvt.rn.bf16x2.f32 %0, %1, %2;" : "=r"(l0) : "f"(r1), "f"(r0));
    asm("cvt.rn.bf16x2.f32 %0, %1, %2;" : "=r"(l1) : "f"(r3), "f"(r2));
    hi.x = h0; hi.y = h1; lo.x = l0; lo.y = l1;
}

#define LDSM4(R, ADDR) \
    asm volatile("ldmatrix.sync.aligned.m8n8.x4.shared.b16 {%0,%1,%2,%3}, [%4];" \
                 : "=r"((R)[0]), "=r"((R)[1]), "=r"((R)[2]), "=r"((R)[3]) : "r"(ADDR))

#define MMA16816(D, A, B) \
    asm volatile("mma.sync.aligned.m16n8k16.row.col.f32.bf16.bf16.f32 " \
                 "{%0,%1,%2,%3}, {%4,%5,%6,%7}, {%8,%9}, {%0,%1,%2,%3};" \
                 : "+f"((D)[0]), "+f"((D)[1]), "+f"((D)[2]), "+f"((D)[3]) \
                 : "r"((A)[0]), "r"((A)[1]), "r"((A)[2]), "r"((A)[3]), \
                   "r"((B)[0]), "r"((B)[1]))

// ================== bf16x3 mma.sync GEMM: C[M,N] = A[M,K] @ B[N,K]^T ========
// fp32 in/out, split on the fly. 128x128 tile, BK=32, double-buffered smem.
// EPI bit0 = +bias[col], bit1 = relu. blockIdx.z selects {A,B,bias,C}.
#define RS 40                       // smem row stride (bf16) -> conflict-free
#define ARR_B ((uint32_t)(128 * RS * 2))   // 10240 bytes per array
#define STG_B (4u * ARR_B)                 // Ah, Al, Bh, Bl per stage
#define MMA_SMEM (2 * (int)STG_B)          // 81920 bytes

template<int EPI>
__global__ __launch_bounds__(256, 1)
void mma_gemm_kernel(const float* A0, const float* A1, const float* A2,
                     const float* B0, const float* B1, const float* B2,
                     const float* bi0, const float* bi1, const float* bi2,
                     float* C0, float* C1, float* C2,
                     int ldc, int K)
{
    extern __shared__ uint8_t sm8[];
    const uint32_t sbase = smem_to_u32(sm8);

    const int z = blockIdx.z;
    const float* A = (z == 0 ? A0 : (z == 1 ? A1 : A2)) + (size_t)blockIdx.x * 128 * K;
    const float* B = (z == 0 ? B0 : (z == 1 ? B1 : B2)) + (size_t)blockIdx.y * 128 * K;
    const float* bias = (z == 0 ? bi0 : (z == 1 ? bi1 : bi2));
    float* C = (z == 0 ? C0 : (z == 1 ? C1 : C2))
               + (size_t)blockIdx.x * 128 * ldc + (size_t)blockIdx.y * 128;

    const int tid = threadIdx.x, lane = tid & 31, wid = tid >> 5;
    const int wm = wid & 1;        // 2 M-slabs of 64
    const int wn = wid >> 1;       // 4 N-slabs of 32

    float acc[4][4][4];
#pragma unroll
    for (int a = 0; a < 4; a++)
#pragma unroll
        for (int b = 0; b < 4; b++)
#pragma unroll
            for (int c = 0; c < 4; c++) acc[a][b][c] = 0.f;

    const int nchunk = K >> 5;
    float4 ld[8];

    // per-thread load/convert coordinates (2048 float4 per chunk: A then B)
    const int cr = (tid & 1023) >> 3 ? 0 : 0;  // (dummy to keep compiler quiet)

    // ---- prologue: load + convert chunk 0 ----
#pragma unroll
    for (int i = 0; i < 8; i++) {
        int e = tid + i * 256;
        int r = (e & 1023) >> 3, c = e & 7;
        const float* src = (i < 4) ? A : B;
        ld[i] = *reinterpret_cast<const float4*>(src + (size_t)r * K + c * 4);
    }
#pragma unroll
    for (int i = 0; i < 8; i++) {
        int e = tid + i * 256;
        int r = (e & 1023) >> 3, c = e & 7;
        uint2 hi, lo; split4(ld[i], hi, lo);
        uint32_t off = (i < 4 ? 0u : 2u * ARR_B) + (uint32_t)(r * RS + c * 4) * 2u;
        *reinterpret_cast<uint2*>(sm8 + off) = hi;
        *reinterpret_cast<uint2*>(sm8 + off + ARR_B) = lo;
    }
    __syncthreads();

    for (int kc = 0; kc < nchunk; kc++) {
        const int s = kc & 1;
        // ---- issue next chunk's global loads (latency hidden by MMAs) ----
        if (kc + 1 < nchunk) {
            const int k0n = (kc + 1) << 5;
#pragma unroll
            for (int i = 0; i < 8; i++) {
                int e = tid + i * 256;
                int r = (e & 1023) >> 3, c = e & 7;
                const float* src = (i < 4) ? A : B;
                ld[i] = *reinterpret_cast<const float4*>(src + (size_t)r * K + k0n + c * 4);
            }
        }
        // ---- MMA on stage s ----
        const uint32_t st = sbase + (uint32_t)s * STG_B;
#pragma unroll
        for (int ks = 0; ks < 2; ks++) {
            const int k0 = ks * 16;
            uint32_t ah[4][4], al[4][4], bh[4][2], bl[4][2];
            // A fragments: rows wm*64 + mt*16 + (lane&15), col k0 + (lane>=16)*8
            const uint32_t a_addr = st +
                (uint32_t)(((wm * 64 + (lane & 15)) * RS + k0 + ((lane >> 4) << 3)) * 2);
#pragma unroll
            for (int mt = 0; mt < 4; mt++) {
                LDSM4(ah[mt], a_addr + (uint32_t)(mt * 16 * RS * 2));
                LDSM4(al[mt], a_addr + ARR_B + (uint32_t)(mt * 16 * RS * 2));
            }
            // B fragments: lanes0-7 n0..7@k0, 8-15 n0..7@k8, 16-23 n8..15@k0, 24-31 n8..15@k8
            const uint32_t b_addr = st + 2u * ARR_B +
                (uint32_t)(((wn * 32 + (lane & 7) + ((lane >> 4) << 3)) * RS
                            + k0 + (((lane >> 3) & 1) << 3)) * 2);
            {
                uint32_t t[4];
                LDSM4(t, b_addr);
                bh[0][0] = t[0]; bh[0][1] = t[1]; bh[1][0] = t[2]; bh[1][1] = t[3];
                LDSM4(t, b_addr + (uint32_t)(16 * RS * 2));
                bh[2][0] = t[0]; bh[2][1] = t[1]; bh[3][0] = t[2]; bh[3][1] = t[3];
                LDSM4(t, b_addr + ARR_B);
                bl[0][0] = t[0]; bl[0][1] = t[1]; bl[1][0] = t[2]; bl[1][1] = t[3];
                LDSM4(t, b_addr + ARR_B + (uint32_t)(16 * RS * 2));
                bl[2][0] = t[0]; bl[2][1] = t[1]; bl[3][0] = t[2]; bl[3][1] = t[3];
            }
#pragma unroll
            for (int mt = 0; mt < 4; mt++)
#pragma unroll
                for (int nt = 0; nt < 4; nt++) {
                    MMA16816(acc[mt][nt], ah[mt], bh[nt]);   // hi*hi
                    MMA16816(acc[mt][nt], ah[mt], bl[nt]);   // hi*lo
                    MMA16816(acc[mt][nt], al[mt], bh[nt]);   // lo*hi
                }
        }
        // ---- convert next chunk into the other stage ----
        if (kc + 1 < nchunk) {
            __syncthreads();
            const uint32_t so = (uint32_t)(s ^ 1) * STG_B;
#pragma unroll
            for (int i = 0; i < 8; i++) {
                int e = tid + i * 256;
                int r = (e & 1023) >> 3, c = e & 7;
                uint2 hi, lo; split4(ld[i], hi, lo);
                uint32_t off = so + (i < 4 ? 0u : 2u * ARR_B)
                             + (uint32_t)(r * RS + c * 4) * 2u;
                *reinterpret_cast<uint2*>(sm8 + off) = hi;
                *reinterpret_cast<uint2*>(sm8 + off + ARR_B) = lo;
            }
            __syncthreads();
        }
    }

    // ---- epilogue: c-frag -> gmem (float2 stores), bias/relu ----
#pragma unroll
    for (int mt = 0; mt < 4; mt++) {
        int row0 = wm * 64 + mt * 16 + (lane >> 2);
#pragma unroll
        for (int nt = 0; nt < 4; nt++) {
            int col = wn * 32 + nt * 8 + (lane & 3) * 2;
            float b0 = 0.f, b1 = 0.f;
            if (EPI & 1) { b0 = bias[blockIdx.y * 128 + col]; b1 = bias[blockIdx.y * 128 + col + 1]; }
            float2 v0, v1;
            v0.x = acc[mt][nt][0] + b0; v0.y = acc[mt][nt][1] + b1;
            v1.x = acc[mt][nt][2] + b0; v1.y = acc[mt][nt][3] + b1;
            if (EPI & 2) {
                v0.x = fmaxf(v0.x, 0.f); v0.y = fmaxf(v0.y, 0.f);
                v1.x = fmaxf(v1.x, 0.f); v1.y = fmaxf(v1.y, 0.f);
            }
            *reinterpret_cast<float2*>(C + (size_t)row0 * ldc + col) = v0;
            *reinterpret_cast<float2*>(C + (size_t)(row0 + 8) * ldc + col) = v1;
        }
    }
    (void)cr;
}

// ================== transpose fp32 [R,C] -> [C,R] ===========================
__global__ __launch_bounds__(256)
void transpose_kernel(const float* __restrict__ src, float* __restrict__ dst, int R, int C)
{
    __shared__ float t[32][33];
    int c0 = blockIdx.x * 32, r0 = blockIdx.y * 32;
    int x = threadIdx.x, y = threadIdx.y;  // 32 x 8
#pragma unroll
    for (int j = 0; j < 32; j += 8)
        t[y + j][x] = src[(size_t)(r0 + y + j) * C + c0 + x];
    __syncthreads();
#pragma unroll
    for (int j = 0; j < 32; j += 8)
        dst[(size_t)(c0 + y + j) * R + r0 + x] = t[x][y + j];
}

// ---------------- agg Linear(384->3) + softmax -> nz ------------------------
__global__ __launch_bounds__(256)
void agg_softmax_kernel(const float* __restrict__ Wagg,
                        const float* __restrict__ bagg,
                        float* __restrict__ out_nz)
{
    __shared__ float sW[3 * ADIM * 3];
    int tid = threadIdx.x;
    for (int i = tid; i < 3 * ADIM * 3; i += 256) sW[i] = Wagg[i];
    __syncthreads();
    int warp = tid >> 5, lane = tid & 31;
    int row = blockIdx.x * 8 + warp;
    const float* zr = g_Z + (size_t)row * (3 * ADIM);
    float p0 = 0.f, p1 = 0.f, p2 = 0.f;
#pragma unroll
    for (int it = 0; it < (3 * ADIM) / 32; it++) {
        int k = it * 32 + lane;
        float zv = zr[k];
        p0 = fmaf(zv, sW[k * 3 + 0], p0);
        p1 = fmaf(zv, sW[k * 3 + 1], p1);
        p2 = fmaf(zv, sW[k * 3 + 2], p2);
    }
#pragma unroll
    for (int off = 16; off; off >>= 1) {
        p0 += __shfl_xor_sync(0xffffffffu, p0, off);
        p1 += __shfl_xor_sync(0xffffffffu, p1, off);
        p2 += __shfl_xor_sync(0xffffffffu, p2, off);
    }
    if (lane == 0) {
        p0 += bagg[0]; p1 += bagg[1]; p2 += bagg[2];
        float m = fmaxf(p0, fmaxf(p1, p2));
        float e0 = __expf(p0 - m), e1 = __expf(p1 - m), e2 = __expf(p2 - m);
        float inv = 1.f / (e0 + e1 + e2);
        float n0 = e0 * inv, n1 = e1 * inv, n2 = e2 * inv;
        g_nz[row * 3 + 0] = n0; g_nz[row * 3 + 1] = n1; g_nz[row * 3 + 2] = n2;
        if (out_nz) {
            out_nz[row * 3 + 0] = n0; out_nz[row * 3 + 1] = n1; out_nz[row * 3 + 2] = n2;
        }
    }
}

// ---------------- adj[r,c] = sum_i nz[c,i] * adj_i[r,c] ---------------------
__global__ __launch_bounds__(256)
void combine_adj_kernel(const float* __restrict__ a0,
                        const float* __restrict__ a1,
                        const float* __restrict__ a2)
{
    size_t idx = (size_t)blockIdx.x * 256 + threadIdx.x;   // float4 index
    int c = (int)(idx % (NN / 4)) * 4;
    float4 v0 = ((const float4*)a0)[idx];
    float4 v1 = ((const float4*)a1)[idx];
    float4 v2 = ((const float4*)a2)[idx];
    float4 r;
    r.x = g_nz[(c + 0) * 3] * v0.x + g_nz[(c + 0) * 3 + 1] * v1.x + g_nz[(c + 0) * 3 + 2] * v2.x;
    r.y = g_nz[(c + 1) * 3] * v0.y + g_nz[(c + 1) * 3 + 1] * v1.y + g_nz[(c + 1) * 3 + 2] * v2.y;
    r.z = g_nz[(c + 2) * 3] * v0.z + g_nz[(c + 2) * 3 + 1] * v1.z + g_nz[(c + 2) * 3 + 2] * v2.z;
    r.w = g_nz[(c + 3) * 3] * v0.w + g_nz[(c + 3) * 3 + 1] * v1.w + g_nz[(c + 3) * 3 + 2] * v2.w;
    ((float4*)g_adj)[idx] = r;
}

// ---------------- attention = row-softmax(adj * S), in place ----------------
__global__ __launch_bounds__(256)
void att_softmax_kernel()
{
    __shared__ float sv[NN];
    __shared__ float red[8];
    int row = blockIdx.x, tid = threadIdx.x;
    const float* ar = g_adj + (size_t)row * NN;
    float* sr = g_S + (size_t)row * NN;

    float m = -3.4e38f;
    for (int j = tid; j < NN; j += 256) {
        float v = ar[j] * sr[j];
        sv[j] = v;
        m = fmaxf(m, v);
    }
#pragma unroll
    for (int off = 16; off; off >>= 1) m = fmaxf(m, __shfl_xor_sync(0xffffffffu, m, off));
    if ((tid & 31) == 0) red[tid >> 5] = m;
    __syncthreads();
    float M = -3.4e38f;
#pragma unroll
    for (int i = 0; i < 8; i++) M = fmaxf(M, red[i]);
    __syncthreads();

    float s = 0.f;
    for (int j = tid; j < NN; j += 256) {
        float e = __expf(sv[j] - M);
        sv[j] = e;
        s += e;
    }
#pragma unroll
    for (int off = 16; off; off >>= 1) s += __shfl_xor_sync(0xffffffffu, s, off);
    if ((tid & 31) == 0) red[tid >> 5] = s;
    __syncthreads();
    float S = 0.f;
#pragma unroll
    for (int i = 0; i < 8; i++) S += red[i];
    float inv = 1.f / S;

    for (int j = tid; j < NN; j += 256) sr[j] = sv[j] * inv;
}

// ---------------- XW2 = X_tilde @ W2  (N=8) ---------------------------------
__global__ __launch_bounds__(256)
void xw2_kernel(const float* __restrict__ W2)
{
    __shared__ float sW[NHID][9];
    int tid = threadIdx.x;
    for (int i = tid; i < NHID * NCLASS; i += 256) sW[i / 8][i % 8] = W2[i];
    __syncthreads();
    int warp = tid >> 5, lane = tid & 31;
    int row = blockIdx.x * 8 + warp;
    const float* xr = g_Xt + (size_t)row * NHID;
    float acc[8] = {0, 0, 0, 0, 0, 0, 0, 0};
#pragma unroll
    for (int it = 0; it < NHID / 32; it++) {
        int k = it * 32 + lane;
        float xv = xr[k];
#pragma unroll
        for (int j = 0; j < 8; j++) acc[j] = fmaf(xv, sW[k][j], acc[j]);
    }
#pragma unroll
    for (int j = 0; j < 8; j++)
#pragma unroll
        for (int off = 16; off; off >>= 1)
            acc[j] += __shfl_xor_sync(0xffffffffu, acc[j], off);
    if (lane == 0) {
#pragma unroll
        for (int j = 0; j < 8; j++) g_XW2[(size_t)row * 8 + j] = acc[j];
    }
}

// ---------------- z = adj @ XW2 + b2 ; softmax rows -> out ------------------
__global__ __launch_bounds__(256)
void z_out_kernel(const float* __restrict__ b2, float* __restrict__ out)
{
    __shared__ float sW[512][9];
    int tid = threadIdx.x, warp = tid >> 5, lane = tid & 31;
    int row = blockIdx.x * 8 + warp;
    const float* ar = g_adj + (size_t)row * NN;
    float acc[8] = {0, 0, 0, 0, 0, 0, 0, 0};
    for (int c0 = 0; c0 < NN; c0 += 512) {
        __syncthreads();
        for (int i = tid; i < 512 * 8; i += 256) sW[i / 8][i % 8] = g_XW2[(size_t)(c0) * 8 + i];
        __syncthreads();
#pragma unroll
        for (int it = 0; it < 16; it++) {
            int k = it * 32 + lane;
            float a = ar[c0 + k];
#pragma unroll
            for (int j = 0; j < 8; j++) acc[j] = fmaf(a, sW[k][j], acc[j]);
        }
    }
#pragma unroll
    for (int j = 0; j < 8; j++)
#pragma unroll
        for (int off = 16; off; off >>= 1)
            acc[j] += __shfl_xor_sync(0xffffffffu, acc[j], off);
    if (lane == 0) {
        float z[8]; float m = -3.4e38f;
#pragma unroll
        for (int j = 0; j < 8; j++) { z[j] = acc[j] + b2[j]; m = fmaxf(m, z[j]); }
        float s = 0.f;
#pragma unroll
        for (int j = 0; j < 8; j++) { z[j] = __expf(z[j] - m); s += z[j]; }
        float inv = 1.f / s;
#pragma unroll
        for (int j = 0; j < 8; j++) out[(size_t)row * 8 + j] = z[j] * inv;
    }
}

// ---------------- launch ----------------------------------------------------
extern "C" void kernel_launch(void* const* d_in, const int* in_sizes, int n_in,
                              void* d_out, int out_size)
{
    const float* adj0 = (const float*)d_in[0];
    const float* adj1 = (const float*)d_in[1];
    const float* adj2 = (const float*)d_in[2];
    const float* feat = (const float*)d_in[3];
    const float* Wa1  = (const float*)d_in[4];
    const float* ba1  = (const float*)d_in[5];
    const float* Wa2  = (const float*)d_in[6];
    const float* ba2  = (const float*)d_in[7];
    const float* Wa3  = (const float*)d_in[8];
    const float* ba3  = (const float*)d_in[9];
    const float* Wagg = (const float*)d_in[10];
    const float* bagg = (const float*)d_in[11];
    const float* W1   = (const float*)d_in[12];
    const float* b1   = (const float*)d_in[13];
    const float* Wq   = (const float*)d_in[14];
    const float* bq   = (const float*)d_in[15];
    const float* Wk   = (const float*)d_in[16];
    const float* bk   = (const float*)d_in[17];
    const float* Wv   = (const float*)d_in[18];
    const float* bv   = (const float*)d_in[19];
    const float* W2   = (const float*)d_in[20];
    const float* b2   = (const float*)d_in[21];
    float* out = (float*)d_out;

    float *adjC, *S, *Z, *XW1, *XW1T, *x, *Q, *Kh, *V, *VT, *Xt;
    float *WaT0, *WaT1, *WaT2, *W1T, *WqT, *WkT, *WvT;
    cudaGetSymbolAddress((void**)&adjC, g_adj);
    cudaGetSymbolAddress((void**)&S,    g_S);
    cudaGetSymbolAddress((void**)&Z,    g_Z);
    cudaGetSymbolAddress((void**)&XW1,  g_XW1);
    cudaGetSymbolAddress((void**)&XW1T, g_XW1T);
    cudaGetSymbolAddress((void**)&x,    g_x);
    cudaGetSymbolAddress((void**)&Q,    g_Q);
    cudaGetSymbolAddress((void**)&Kh,   g_Kh);
    cudaGetSymbolAddress((void**)&V,    g_V);
    cudaGetSymbolAddress((void**)&VT,   g_VT);
    cudaGetSymbolAddress((void**)&Xt,   g_Xt);
    cudaGetSymbolAddress((void**)&WaT0, g_WaT);
    WaT1 = WaT0 + (size_t)ADIM * NN;
    WaT2 = WaT1 + (size_t)ADIM * NN;
    cudaGetSymbolAddress((void**)&W1T, g_W1T);
    cudaGetSymbolAddress((void**)&WqT, g_WqT);
    cudaGetSymbolAddress((void**)&WkT, g_WkT);
    cudaGetSymbolAddress((void**)&WvT, g_WvT);

    cudaFuncSetAttribute(mma_gemm_kernel<0>, cudaFuncAttributeMaxDynamicSharedMemorySize, MMA_SMEM);
    cudaFuncSetAttribute(mma_gemm_kernel<1>, cudaFuncAttributeMaxDynamicSharedMemorySize, MMA_SMEM);
    cudaFuncSetAttribute(mma_gemm_kernel<2>, cudaFuncAttributeMaxDynamicSharedMemorySize, MMA_SMEM);
    cudaFuncSetAttribute(mma_gemm_kernel<3>, cudaFuncAttributeMaxDynamicSharedMemorySize, MMA_SMEM);

    dim3 tb(32, 8);
    // weight transposes ([K,N] -> [N,K] for the MMA B operand)
    transpose_kernel<<<dim3(ADIM / 32, NN / 32), tb>>>(Wa1, WaT0, NN, ADIM);
    transpose_kernel<<<dim3(ADIM / 32, NN / 32), tb>>>(Wa2, WaT1, NN, ADIM);
    transpose_kernel<<<dim3(ADIM / 32, NN / 32), tb>>>(Wa3, WaT2, NN, ADIM);
    transpose_kernel<<<dim3(NHID / 32, NFEAT / 32), tb>>>(W1, W1T, NFEAT, NHID);
    transpose_kernel<<<dim3(NHID / 32, NHID / 32), tb>>>(Wq, WqT, NHID, NHID);
    transpose_kernel<<<dim3(NHID / 32, NHID / 32), tb>>>(Wk, WkT, NHID, NHID);
    transpose_kernel<<<dim3(NHID / 32, NHID / 32), tb>>>(Wv, WvT, NHID, NHID);

    // 1) z1|z2|z3 : adj_i @ Wa_i + ba_i   (fused over blockIdx.z)
    mma_gemm_kernel<1><<<dim3(NN / 128, 1, 3), 256, MMA_SMEM>>>(
        adj0, adj1, adj2, WaT0, WaT1, WaT2, ba1, ba2, ba3,
        Z, Z + ADIM, Z + 2 * ADIM, 3 * ADIM, NN);

    // 2) nz = softmax(concat(z) @ Wagg + bagg); also second output
    float* out_nz = (out_size >= NN * (NCLASS + 3)) ? out + (size_t)NN * NCLASS : nullptr;
    agg_softmax_kernel<<<NN / 8, 256>>>(Wagg, bagg, out_nz);

    // 3) adj = column-weighted combination (fp32)
    combine_adj_kernel<<<(NN / 4) * (NN / 256), 256>>>(adj0, adj1, adj2);

    // 4) XW1 = features @ W1
    mma_gemm_kernel<0><<<dim3(NN / 128, NHID / 128, 1), 256, MMA_SMEM>>>(
        feat, feat, feat, W1T, W1T, W1T, nullptr, nullptr, nullptr,
        XW1, XW1, XW1, NHID, NFEAT);
    transpose_kernel<<<dim3(NHID / 32, NN / 32), tb>>>(XW1, XW1T, NN, NHID);

    // 5) x = relu(adj @ XW1 + b1)
    mma_gemm_kernel<3><<<dim3(NN / 128, NHID / 128, 1), 256, MMA_SMEM>>>(
        adjC, adjC, adjC, XW1T, XW1T, XW1T, b1, b1, b1,
        x, x, x, NHID, NN);

    // 6) Q, K, V fused over blockIdx.z
    mma_gemm_kernel<1><<<dim3(NN / 128, NHID / 128, 3), 256, MMA_SMEM>>>(
        x, x, x, WqT, WkT, WvT, bq, bk, bv,
        Q, Kh, V, NHID, NHID);
    transpose_kernel<<<dim3(NHID / 32, NN / 32), tb>>>(V, VT, NN, NHID);

    // 7) S = Q @ K^T   (K_h is already [N,K] for the B operand)
    mma_gemm_kernel<0><<<dim3(NN / 128, NN / 128, 1), 256, MMA_SMEM>>>(
        Q, Q, Q, Kh, Kh, Kh, nullptr, nullptr, nullptr,
        S, S, S, NN, NHID);

    // 8) attention = row-softmax(adj * S)   (gcn_norm == identity, skipped)
    att_softmax_kernel<<<NN, 256>>>();

    // 9) X_tilde = relu(attention @ V)
    mma_gemm_kernel<2><<<dim3(NN / 128, NHID / 128, 1), 256, MMA_SMEM>>>(
        S, S, S, VT, VT, VT, nullptr, nullptr, nullptr,
        Xt, Xt, Xt, NHID, NN);

    // 10) XW2 = X_tilde @ W2
    xw2_kernel<<<NN / 8, 256>>>(W2);

    // 11) z = adj @ XW2 + b2 ; row softmax -> out[0 : N*8)
    z_out_kernel<<<NN / 8, 256>>>(b2, out);
}